// round 3
// baseline (speedup 1.0000x reference)
#include <cuda_runtime.h>

// Fixed shapes
#define HH   512
#define WW   512
#define HWSZ (HH * WW)          // 262144 = 2^18
#define BB   4
#define CC   21
#define NPIX (BB * HWSZ)        // 1048576
#define TILE 64                 // 64x64 tiles
#define TPP  (TILE * TILE)      // 4096
#define TILES_X (WW / TILE)     // 8
#define NTILES (BB * TILES_X * TILES_X)  // 256
#define FBLOCKS 4096

// Static device scratch
__device__ int           g_labels[NPIX];
__device__ int           g_counts[NPIX];
__device__ unsigned char g_tgt[NPIX];
__device__ float         g_ce[NPIX];
__device__ float         g_partial[FBLOCKS];
__device__ int           g_is32;

// ---------------------------------------------------------------------------
// dtype detect: one block scans first 256 odd 32-bit words. int64 targets
// (values 0..20) have zero high words; int32 targets are nonzero w.p. 20/21
// per word -> P(false int64) = 21^-256 ~ 0.
// ---------------------------------------------------------------------------
__global__ void k_detect(const unsigned* __restrict__ t) {
    unsigned v = t[2 * threadIdx.x + 1];
    int any = __syncthreads_or(v != 0u);
    if (threadIdx.x == 0) g_is32 = any;
}

// ---------------------------------------------------------------------------
// Shared-memory union-find (tile-local)
// ---------------------------------------------------------------------------
__device__ __forceinline__ int sfind(volatile int* lab, int x) {
    int y = lab[x];
    while (y != x) { x = y; y = lab[x]; }
    return x;
}
__device__ __forceinline__ void sunite(int* lab, int a, int b) {
    while (true) {
        a = sfind(lab, a);
        b = sfind(lab, b);
        if (a == b) return;
        int mx = a > b ? a : b;
        int mn = a > b ? b : a;
        int old = atomicMin(&lab[mx], mn);
        if (old == mx) return;
        a = old; b = mn;
    }
}
// Global union-find
__device__ __forceinline__ int gfind(int x) {
    int y = g_labels[x];
    while (y != x) { x = y; y = g_labels[x]; }
    return x;
}
__device__ __forceinline__ void gunite(int a, int b) {
    while (true) {
        a = gfind(a);
        b = gfind(b);
        if (a == b) return;
        int mx = a > b ? a : b;
        int mn = a > b ? b : a;
        int old = atomicMin(&g_labels[mx], mn);
        if (old == mx) return;
        a = old; b = mn;
    }
}

// ---------------------------------------------------------------------------
// Fused normalize + tile-local CCL (64x64 tile, 256 threads, 16 px/thread).
// Reads raw targets (either dtype), writes g_tgt, zeroes g_counts slice,
// resolves intra-tile components in smem, writes global labels.
// ---------------------------------------------------------------------------
__global__ void __launch_bounds__(256) k_local(const void* __restrict__ t) {
    __shared__ unsigned char st[TPP];
    __shared__ int           sl[TPP];

    int tile = blockIdx.x;
    int img  = tile >> 6;            // 64 tiles per image
    int ty   = (tile >> 3) & 7;
    int tx   = tile & 7;
    int base = img * HWSZ + (ty * TILE) * WW + tx * TILE;
    int is32 = g_is32;

#pragma unroll
    for (int k = 0; k < 16; k++) {
        int i  = threadIdx.x + k * 256;
        int gp = base + (i >> 6) * WW + (i & 63);
        int v  = is32 ? ((const int*)t)[gp]
                      : (int)((const long long*)t)[gp];
        st[i] = (unsigned char)v;
        sl[i] = i;
        g_tgt[gp]    = (unsigned char)v;
        g_counts[gp] = 0;
    }
    __syncthreads();

#pragma unroll
    for (int k = 0; k < 16; k++) {
        int i = threadIdx.x + k * 256;
        int c = st[i];
        if (c) {
            if ((i & 63) != 63 && st[i + 1]  == c) sunite(sl, i, i + 1);
            if (i < TPP - TILE && st[i + 64] == c) sunite(sl, i, i + 64);
        }
    }
    __syncthreads();

#pragma unroll
    for (int k = 0; k < 16; k++) {
        int i  = threadIdx.x + k * 256;
        int r  = sfind(sl, i);
        int gp = base + (i >> 6) * WW + (i & 63);
        g_labels[gp] = base + (r >> 6) * WW + (r & 63);
    }
}

// ---------------------------------------------------------------------------
// Cross-tile boundary merges: 7 vertical + 7 horizontal seams per image,
// 512 edges each -> 28672 total edges.
// ---------------------------------------------------------------------------
#define EDGES_PER_DIR (7 * 512)
#define EDGES_PER_IMG (2 * EDGES_PER_DIR)
#define NEDGES (BB * EDGES_PER_IMG)

__global__ void k_boundary() {
    int e = blockIdx.x * blockDim.x + threadIdx.x;
    if (e >= NEDGES) return;
    int img = e / EDGES_PER_IMG;
    int rem = e % EDGES_PER_IMG;
    int dir = rem / EDGES_PER_DIR;
    int k   = rem % EDGES_PER_DIR;
    int b   = k >> 9;          // seam 0..6
    int t   = k & 511;

    int p, q;
    if (dir == 0) {            // vertical seam: columns b*64+63 | b*64+64
        int x = b * TILE + (TILE - 1);
        p = img * HWSZ + t * WW + x;
        q = p + 1;
    } else {                   // horizontal seam
        int y = b * TILE + (TILE - 1);
        p = img * HWSZ + y * WW + t;
        q = p + WW;
    }
    int c = g_tgt[p];
    if (c && g_tgt[q] == c) gunite(p, q);
}

// ---------------------------------------------------------------------------
// Fused compress + count
// ---------------------------------------------------------------------------
__global__ void k_compress_count() {
    int p = blockIdx.x * blockDim.x + threadIdx.x;
    if (p >= NPIX) return;
    int r = gfind(p);
    g_labels[p] = r;
    if (g_tgt[p]) atomicAdd(&g_counts[r], 1);
}

// ---------------------------------------------------------------------------
// Per-pixel cross-entropy (independent of CCL) -> g_ce.  HBM-bound 88MB pass.
// Reads raw targets directly (dtype via g_is32).
// ---------------------------------------------------------------------------
__global__ void __launch_bounds__(256) k_ce(const float* __restrict__ logits,
                                            const void* __restrict__ t) {
    int p   = blockIdx.x * 256 + threadIdx.x;
    int b   = p >> 18;
    int pix = p & (HWSZ - 1);
    const float* base = logits + ((size_t)b * CC) * HWSZ + pix;

    int ti = g_is32 ? ((const int*)t)[p]
                    : (int)((const long long*)t)[p];

    float v[CC];
    float m = -1e30f, tv = 0.f;
#pragma unroll
    for (int c = 0; c < CC; c++) {
        v[c] = base[(size_t)c * HWSZ];
        m = fmaxf(m, v[c]);
        if (c == ti) tv = v[c];
    }
    float s = 0.f;
#pragma unroll
    for (int c = 0; c < CC; c++) s += __expf(v[c] - m);

    g_ce[p] = m + __logf(s) - tv;
}

// ---------------------------------------------------------------------------
// Join: apply dynamic weights to CE and block-reduce.
// ---------------------------------------------------------------------------
__global__ void __launch_bounds__(256) k_weight_reduce() {
    __shared__ float sh[256];
    const float inv_log501 = 0.16085946f;  // 1/ln(501)

    int p  = blockIdx.x * 256 + threadIdx.x;
    int ti = g_tgt[p];
    float wgt = 1.f;
    if (ti > 0) {
        int sz = g_counts[g_labels[p]];
        if (sz < 500)
            wgt = 3.f * __logf((float)sz + 1.f) * inv_log501;
    }
    sh[threadIdx.x] = g_ce[p] * wgt;
    __syncthreads();
#pragma unroll
    for (int s = 128; s > 0; s >>= 1) {
        if (threadIdx.x < s) sh[threadIdx.x] += sh[threadIdx.x + s];
        __syncthreads();
    }
    if (threadIdx.x == 0) g_partial[blockIdx.x] = sh[0];
}

__global__ void k_reduce(float* __restrict__ out) {
    __shared__ float sh[256];
    float a = 0.f;
    for (int i = threadIdx.x; i < FBLOCKS; i += 256) a += g_partial[i];
    sh[threadIdx.x] = a;
    __syncthreads();
#pragma unroll
    for (int s = 128; s > 0; s >>= 1) {
        if (threadIdx.x < s) sh[threadIdx.x] += sh[threadIdx.x + s];
        __syncthreads();
    }
    if (threadIdx.x == 0) out[0] = sh[0] * (1.f / (float)NPIX);
}

// ---------------------------------------------------------------------------
// Launch: fork CCL branch onto a side stream so it overlaps the HBM-bound
// CE pass; join before the weight+reduce epilogue. Streams/events are host
// resources created once (no device memory involved).
// ---------------------------------------------------------------------------
extern "C" void kernel_launch(void* const* d_in, const int* in_sizes, int n_in,
                              void* d_out, int out_size) {
    const float* logits = (const float*)d_in[0];
    const void*  tgt    = d_in[1];
    float*       out    = (float*)d_out;

    static cudaStream_t sB = nullptr;
    static cudaEvent_t  evFork = nullptr, evJoin = nullptr;
    if (!sB) {
        cudaStreamCreateWithFlags(&sB, cudaStreamNonBlocking);
        cudaEventCreateWithFlags(&evFork, cudaEventDisableTiming);
        cudaEventCreateWithFlags(&evJoin, cudaEventDisableTiming);
    }

    const int T = 256;

    // main stream: dtype detect, then fork
    k_detect<<<1, T>>>((const unsigned*)tgt);
    cudaEventRecord(evFork, 0);
    cudaStreamWaitEvent(sB, evFork, 0);

    // branch B (side stream): CCL chain
    k_local         <<<NTILES, T, 0, sB>>>(tgt);
    k_boundary      <<<(NEDGES + T - 1) / T, T, 0, sB>>>();
    k_compress_count<<<NPIX / T, T, 0, sB>>>();
    cudaEventRecord(evJoin, sB);

    // branch A (main stream): HBM-bound CE pass
    k_ce<<<FBLOCKS, T>>>(logits, tgt);

    // join + epilogue
    cudaStreamWaitEvent(0, evJoin, 0);
    k_weight_reduce<<<FBLOCKS, T>>>();
    k_reduce<<<1, T>>>(out);
}